// round 4
// baseline (speedup 1.0000x reference)
#include <cuda_runtime.h>
#include <math_constants.h>

#define Bc   64
#define Tc   256
#define Cn   64
#define Hn   8
#define HSn  8
#define Ln   10
#define DFF  256
#define VOC  8000
#define BT   (Bc*Tc)
#define EPSF 1e-5f

#define SZ_XC (BT*Cn)
#define SZ_FF (BT*DFF)
__device__ float g_scratch[SZ_XC*6 + SZ_FF];

typedef unsigned long long u64;

__device__ __forceinline__ u64 pk2(float x, float y){
    u64 r; asm("mov.b64 %0,{%1,%2};" : "=l"(r) : "f"(x), "f"(y)); return r;
}
__device__ __forceinline__ void upk2(u64 p, float& x, float& y){
    asm("mov.b64 {%0,%1},%2;" : "=f"(x), "=f"(y) : "l"(p));
}
__device__ __forceinline__ void ffma2(u64& a, u64 b, u64 c){
    asm("fma.rn.f32x2 %0,%1,%2,%0;" : "+l"(a) : "l"(b), "l"(c));
}

// ---------------------------------------------------------------------------
// GEMM: C[M,N] = A[M,K] @ W[K,N]. BM=64, BN=64, BK=64, 128 threads.
// Thread tile 4 rows x 8 cols; accumulators packed as column-pairs (f32x2),
// so B pairs load directly as u64 from smem (no packing MOVs).
// EPI 0: (+bias) store.  EPI 1: (+bias) relu store.
// EPI 2: (+bias +res) -> Cout, rowwise LayerNorm -> Hout (N must be 64).
// ---------------------------------------------------------------------------
template<int EPI>
__device__ __forceinline__ void gemm_body(
    const float* __restrict__ A, const float* __restrict__ W,
    const float* __restrict__ bias, const float* __restrict__ res,
    float* __restrict__ Cout, float* __restrict__ Hout,
    const float* __restrict__ lng, const float* __restrict__ lnb,
    int N, int K)
{
    __shared__ float As[64][66];   // transposed A tile, stride 66 (8B-aligned rows)
    __shared__ float Ws[64][64];
    const int tid  = threadIdx.x;
    const int row0 = blockIdx.y * 64;
    const int col0 = blockIdx.x * 64;
    const int tx   = tid & 7;      // col group: cols tx*8 .. tx*8+7
    const int ty   = tid >> 3;     // row group: rows ty*4 .. ty*4+3

    u64 acc[4][4];                 // [row i][col-pair j2] -> cols tx*8+2*j2, +1
    #pragma unroll
    for (int i = 0; i < 4; i++)
        #pragma unroll
        for (int j = 0; j < 4; j++) acc[i][j] = 0ull;

    for (int k0 = 0; k0 < K; k0 += 64) {
        #pragma unroll
        for (int v = 0; v < 8; v++) {            // A tile 64x64, transposed store
            int idx = tid + v * 128;
            int m   = idx >> 4;
            int k4  = (idx & 15) * 4;
            float4 t = *(const float4*)&A[(row0 + m) * K + k0 + k4];
            As[k4+0][m] = t.x; As[k4+1][m] = t.y; As[k4+2][m] = t.z; As[k4+3][m] = t.w;
        }
        #pragma unroll
        for (int v = 0; v < 8; v++) {            // W tile 64x64
            int idx = tid + v * 128;
            int k   = idx >> 4;
            int n4  = (idx & 15) * 4;
            *(float4*)&Ws[k][n4] = *(const float4*)&W[(k0 + k) * N + col0 + n4];
        }
        __syncthreads();
        #pragma unroll 8
        for (int k = 0; k < 64; k++) {
            u64 ap01 = *(const u64*)&As[k][ty * 4];
            u64 ap23 = *(const u64*)&As[k][ty * 4 + 2];
            float a0, a1, a2, a3;
            upk2(ap01, a0, a1);
            upk2(ap23, a2, a3);
            u64 ad0 = pk2(a0, a0), ad1 = pk2(a1, a1);
            u64 ad2 = pk2(a2, a2), ad3 = pk2(a3, a3);
            u64 bd0 = *(const u64*)&Ws[k][tx * 8];
            u64 bd1 = *(const u64*)&Ws[k][tx * 8 + 2];
            u64 bd2 = *(const u64*)&Ws[k][tx * 8 + 4];
            u64 bd3 = *(const u64*)&Ws[k][tx * 8 + 6];
            ffma2(acc[0][0], ad0, bd0); ffma2(acc[0][1], ad0, bd1);
            ffma2(acc[0][2], ad0, bd2); ffma2(acc[0][3], ad0, bd3);
            ffma2(acc[1][0], ad1, bd0); ffma2(acc[1][1], ad1, bd1);
            ffma2(acc[1][2], ad1, bd2); ffma2(acc[1][3], ad1, bd3);
            ffma2(acc[2][0], ad2, bd0); ffma2(acc[2][1], ad2, bd1);
            ffma2(acc[2][2], ad2, bd2); ffma2(acc[2][3], ad2, bd3);
            ffma2(acc[3][0], ad3, bd0); ffma2(acc[3][1], ad3, bd1);
            ffma2(acc[3][2], ad3, bd2); ffma2(acc[3][3], ad3, bd3);
        }
        __syncthreads();
    }

    const int cb = col0 + tx * 8;
    float bj[8];
    #pragma unroll
    for (int j = 0; j < 8; j++) bj[j] = bias ? bias[cb + j] : 0.0f;

    float gj[8], eb[8];
    if (EPI == 2) {
        float4 g0 = *(const float4*)&lng[tx*8], g1 = *(const float4*)&lng[tx*8+4];
        float4 e0 = *(const float4*)&lnb[tx*8], e1 = *(const float4*)&lnb[tx*8+4];
        gj[0]=g0.x; gj[1]=g0.y; gj[2]=g0.z; gj[3]=g0.w; gj[4]=g1.x; gj[5]=g1.y; gj[6]=g1.z; gj[7]=g1.w;
        eb[0]=e0.x; eb[1]=e0.y; eb[2]=e0.z; eb[3]=e0.w; eb[4]=e1.x; eb[5]=e1.y; eb[6]=e1.z; eb[7]=e1.w;
    }

    #pragma unroll
    for (int i = 0; i < 4; i++) {
        int r = row0 + ty * 4 + i;
        float c8[8];
        #pragma unroll
        for (int j2 = 0; j2 < 4; j2++) upk2(acc[i][j2], c8[2*j2], c8[2*j2+1]);
        #pragma unroll
        for (int j = 0; j < 8; j++) c8[j] += bj[j];

        if (EPI == 1) {
            #pragma unroll
            for (int j = 0; j < 8; j++) c8[j] = fmaxf(c8[j], 0.0f);
        }
        if (EPI == 2) {
            float4 ra = *(const float4*)&res[r*64 + cb];
            float4 rb = *(const float4*)&res[r*64 + cb + 4];
            c8[0]+=ra.x; c8[1]+=ra.y; c8[2]+=ra.z; c8[3]+=ra.w;
            c8[4]+=rb.x; c8[5]+=rb.y; c8[6]+=rb.z; c8[7]+=rb.w;
            float s1 = 0.f, s2 = 0.f;
            #pragma unroll
            for (int j = 0; j < 8; j++) { s1 += c8[j]; s2 += c8[j]*c8[j]; }
            #pragma unroll
            for (int o = 1; o < 8; o <<= 1) {
                s1 += __shfl_xor_sync(0xFFFFFFFFu, s1, o);
                s2 += __shfl_xor_sync(0xFFFFFFFFu, s2, o);
            }
            float mu = s1 * (1.f/64.f);
            float rs = rsqrtf(s2 * (1.f/64.f) - mu*mu + EPSF);
            *(float4*)&Cout[r*64 + cb]     = make_float4(c8[0], c8[1], c8[2], c8[3]);
            *(float4*)&Cout[r*64 + cb + 4] = make_float4(c8[4], c8[5], c8[6], c8[7]);
            float h8[8];
            #pragma unroll
            for (int j = 0; j < 8; j++) h8[j] = (c8[j] - mu) * rs * gj[j] + eb[j];
            *(float4*)&Hout[r*64 + cb]     = make_float4(h8[0], h8[1], h8[2], h8[3]);
            *(float4*)&Hout[r*64 + cb + 4] = make_float4(h8[4], h8[5], h8[6], h8[7]);
        } else {
            *(float4*)&Cout[r*N + cb]     = make_float4(c8[0], c8[1], c8[2], c8[3]);
            *(float4*)&Cout[r*N + cb + 4] = make_float4(c8[4], c8[5], c8[6], c8[7]);
        }
    }
}

template<int EPI>
__global__ void __launch_bounds__(128)
gemm_k(const float* __restrict__ A, const float* __restrict__ W,
       const float* __restrict__ bias, const float* __restrict__ res,
       float* __restrict__ Cout, float* __restrict__ Hout,
       const float* __restrict__ lng, const float* __restrict__ lnb,
       int N, int K)
{
    gemm_body<EPI>(A, W, bias, res, Cout, Hout, lng, lnb, N, K);
}

__global__ void __launch_bounds__(128)
qkv_k(const float* __restrict__ A,
      const float* __restrict__ wq, const float* __restrict__ wk, const float* __restrict__ wv,
      float* __restrict__ q, float* __restrict__ k, float* __restrict__ v)
{
    const float* W = (blockIdx.z == 0) ? wq : (blockIdx.z == 1) ? wk : wv;
    float*       O = (blockIdx.z == 0) ? q  : (blockIdx.z == 1) ? k  : v;
    gemm_body<0>(A, W, nullptr, nullptr, O, nullptr, nullptr, nullptr, 64, 64);
}

// ---------------------------------------------------------------------------
// Embedding + first LayerNorm: warp per row.
// ---------------------------------------------------------------------------
__global__ void __launch_bounds__(256)
embed_ln_k(const int* __restrict__ idx, const float* __restrict__ tok,
           const float* __restrict__ pos, const float* __restrict__ g,
           const float* __restrict__ b, float* __restrict__ x, float* __restrict__ h)
{
    int row  = blockIdx.x * 8 + (threadIdx.x >> 5);
    int lane = threadIdx.x & 31;
    int t    = row & (Tc - 1);
    int tr   = idx[row];
    float v0 = tok[tr*Cn + lane]      + pos[t*Cn + lane];
    float v1 = tok[tr*Cn + lane + 32] + pos[t*Cn + lane + 32];
    float sum = v0 + v1;
    #pragma unroll
    for (int o = 16; o; o >>= 1) sum += __shfl_xor_sync(0xFFFFFFFFu, sum, o);
    float mu = sum * (1.f/64.f);
    float d0 = v0 - mu, d1 = v1 - mu;
    float vs = d0*d0 + d1*d1;
    #pragma unroll
    for (int o = 16; o; o >>= 1) vs += __shfl_xor_sync(0xFFFFFFFFu, vs, o);
    float r = rsqrtf(vs * (1.f/64.f) + EPSF);
    x[row*Cn + lane]      = v0;
    x[row*Cn + lane + 32] = v1;
    h[row*Cn + lane]      = d0*r*g[lane]    + b[lane];
    h[row*Cn + lane + 32] = d1*r*g[lane+32] + b[lane+32];
}

// ---------------------------------------------------------------------------
// Attention: block per (b,h). Bounded scores -> direct exp, no max chain.
// Each warp handles 4 query rows; K/V staged in smem.
// ---------------------------------------------------------------------------
__global__ void __launch_bounds__(256)
attn_kernel(const float* __restrict__ q, const float* __restrict__ kk,
            const float* __restrict__ vv, float* __restrict__ oo)
{
    int bh = blockIdx.x;
    int b  = bh >> 3;
    int h  = bh & 7;
    __shared__ float ks[Tc][12];
    __shared__ float vs[Tc][12];

    int tid  = threadIdx.x;
    int warp = tid >> 5;
    int lane = tid & 31;
    int base = b * Tc * Cn + h * HSn;

    {
        int r = tid;
        float4 a = *(const float4*)&kk[base + r*Cn];
        float4 c = *(const float4*)&kk[base + r*Cn + 4];
        *(float4*)&ks[r][0] = a; *(float4*)&ks[r][4] = c;
        a = *(const float4*)&vv[base + r*Cn];
        c = *(const float4*)&vv[base + r*Cn + 4];
        *(float4*)&vs[r][0] = a; *(float4*)&vs[r][4] = c;
    }
    __syncthreads();

    for (int rq = warp; rq < Tc/4; rq += 8) {
        int i0 = rq * 4;
        float qd[4][8];
        #pragma unroll
        for (int r2 = 0; r2 < 4; r2++) {
            float4 a = *(const float4*)&q[base + (i0+r2)*Cn];
            float4 c = *(const float4*)&q[base + (i0+r2)*Cn + 4];
            qd[r2][0]=a.x*0.125f; qd[r2][1]=a.y*0.125f; qd[r2][2]=a.z*0.125f; qd[r2][3]=a.w*0.125f;
            qd[r2][4]=c.x*0.125f; qd[r2][5]=c.y*0.125f; qd[r2][6]=c.z*0.125f; qd[r2][7]=c.w*0.125f;
        }
        float s[4] = {0.f, 0.f, 0.f, 0.f};
        float o[4][8];
        #pragma unroll
        for (int r2 = 0; r2 < 4; r2++)
            #pragma unroll
            for (int d = 0; d < 8; d++) o[r2][d] = 0.f;

        int imax = i0 + 3;
        for (int j = lane; j <= imax; j += 32) {
            float4 ka = *(const float4*)&ks[j][0];
            float4 kb = *(const float4*)&ks[j][4];
            float4 va = *(const float4*)&vs[j][0];
            float4 vb = *(const float4*)&vs[j][4];
            float kj[8] = {ka.x,ka.y,ka.z,ka.w,kb.x,kb.y,kb.z,kb.w};
            float vj[8] = {va.x,va.y,va.z,va.w,vb.x,vb.y,vb.z,vb.w};
            #pragma unroll
            for (int r2 = 0; r2 < 4; r2++) {
                float sc = 0.f;
                #pragma unroll
                for (int d = 0; d < 8; d++) sc = fmaf(qd[r2][d], kj[d], sc);
                if (j <= i0 + r2) {
                    float e = __expf(sc);
                    s[r2] += e;
                    #pragma unroll
                    for (int d = 0; d < 8; d++) o[r2][d] = fmaf(e, vj[d], o[r2][d]);
                }
            }
        }
        #pragma unroll
        for (int r2 = 0; r2 < 4; r2++) {
            #pragma unroll
            for (int off = 16; off; off >>= 1) {
                s[r2] += __shfl_xor_sync(0xFFFFFFFFu, s[r2], off);
                #pragma unroll
                for (int d = 0; d < 8; d++)
                    o[r2][d] += __shfl_xor_sync(0xFFFFFFFFu, o[r2][d], off);
            }
            if (lane == 0) {
                float inv = 1.f / s[r2];
                *(float4*)&oo[base + (i0+r2)*Cn]     = make_float4(o[r2][0]*inv, o[r2][1]*inv, o[r2][2]*inv, o[r2][3]*inv);
                *(float4*)&oo[base + (i0+r2)*Cn + 4] = make_float4(o[r2][4]*inv, o[r2][5]*inv, o[r2][6]*inv, o[r2][7]*inv);
            }
        }
    }
}

// ---------------------------------------------------------------------------
// Launch
// ---------------------------------------------------------------------------
extern "C" void kernel_launch(void* const* d_in, const int* in_sizes, int n_in,
                              void* d_out, int out_size)
{
    const int*   idx    = (const int*)  d_in[0];
    const float* tok    = (const float*)d_in[1];
    const float* pos    = (const float*)d_in[2];
    const float* wq     = (const float*)d_in[3];
    const float* wk     = (const float*)d_in[4];
    const float* wv     = (const float*)d_in[5];
    const float* w_proj = (const float*)d_in[6];
    const float* b_proj = (const float*)d_in[7];
    const float* ln1_g  = (const float*)d_in[8];
    const float* ln1_b  = (const float*)d_in[9];
    const float* ln2_g  = (const float*)d_in[10];
    const float* ln2_b  = (const float*)d_in[11];
    const float* w1     = (const float*)d_in[12];
    const float* b1     = (const float*)d_in[13];
    const float* w2     = (const float*)d_in[14];
    const float* b2     = (const float*)d_in[15];
    const float* lnf_g  = (const float*)d_in[16];
    const float* lnf_b  = (const float*)d_in[17];
    const float* w_head = (const float*)d_in[18];
    const float* b_head = (const float*)d_in[19];
    float* out = (float*)d_out;

    void* sp = nullptr;
    cudaGetSymbolAddress(&sp, g_scratch);
    float* g_x  = (float*)sp;
    float* g_h  = g_x + SZ_XC;
    float* g_q  = g_h + SZ_XC;
    float* g_k  = g_q + SZ_XC;
    float* g_v  = g_k + SZ_XC;
    float* g_o  = g_v + SZ_XC;
    float* g_ff = g_o + SZ_XC;

    embed_ln_k<<<BT/8, 256>>>(idx, tok, pos, ln1_g, ln1_b, g_x, g_h);

    for (int l = 0; l < Ln; l++) {
        qkv_k<<<dim3(1, 256, 3), 128>>>(g_h, wq + l*Cn*Cn, wk + l*Cn*Cn, wv + l*Cn*Cn,
                                        g_q, g_k, g_v);
        attn_kernel<<<Bc*Hn, 256>>>(g_q, g_k, g_v, g_o);
        gemm_k<2><<<dim3(1, 256), 128>>>(g_o, w_proj + l*Cn*Cn, b_proj + l*Cn, g_x,
                                         g_x, g_h, ln2_g + l*Cn, ln2_b + l*Cn, 64, 64);
        gemm_k<1><<<dim3(4, 256), 128>>>(g_h, w1 + l*Cn*DFF, b1 + l*DFF, nullptr,
                                         g_ff, nullptr, nullptr, nullptr, DFF, 64);
        const float* ng = (l < Ln-1) ? ln1_g + (l+1)*Cn : lnf_g;
        const float* nb = (l < Ln-1) ? ln1_b + (l+1)*Cn : lnf_b;
        gemm_k<2><<<dim3(1, 256), 128>>>(g_ff, w2 + l*DFF*Cn, b2 + l*Cn, g_x,
                                         g_x, g_h, ng, nb, 64, 256);
    }

    gemm_k<0><<<dim3(VOC/64, 256), 128>>>(g_h, w_head, b_head, nullptr,
                                          out, nullptr, nullptr, nullptr, VOC, 64);
}

// round 6
// speedup vs baseline: 1.0224x; 1.0224x over previous
#include <cuda_runtime.h>
#include <math_constants.h>

#define Bc   64
#define Tc   256
#define Cn   64
#define Hn   8
#define HSn  8
#define Ln   10
#define DFF  256
#define VOC  8000
#define BT   (Bc*Tc)
#define EPSF 1e-5f

#define SZ_XC (BT*Cn)
#define SZ_FF (BT*DFF)
__device__ float g_scratch[SZ_XC*6 + SZ_FF];

typedef unsigned long long u64;

__device__ __forceinline__ u64 pk2(float x, float y){
    u64 r; asm("mov.b64 %0,{%1,%2};" : "=l"(r) : "f"(x), "f"(y)); return r;
}
__device__ __forceinline__ void upk2(u64 p, float& x, float& y){
    asm("mov.b64 {%0,%1},%2;" : "=f"(x), "=f"(y) : "l"(p));
}
__device__ __forceinline__ void ffma2(u64& a, u64 b, u64 c){
    asm("fma.rn.f32x2 %0,%1,%2,%0;" : "+l"(a) : "l"(b), "l"(c));
}

// ---------------------------------------------------------------------------
// Single-stage GEMM: C[M,N] = A[M,K] @ W[K,N]. BM=64, BN=64, whole K resident
// in smem (K in {64,256}). 128 threads; thread tile 4 rows x 8 cols with
// row-pair f32x2 accumulators. One __syncthreads total, then a pure
// pipe-bound FFMA2 loop.
// EPI 0: (+bias) store.  EPI 1: (+bias) relu store.
// EPI 2: (+bias +res) -> Cout, rowwise LayerNorm -> Hout (N must be 64).
// ---------------------------------------------------------------------------
template<int K, int EPI>
__global__ void __launch_bounds__(128)
gemm_k(const float* __restrict__ A, const float* __restrict__ W,
       const float* __restrict__ bias, const float* __restrict__ res,
       float* __restrict__ Cout, float* __restrict__ Hout,
       const float* __restrict__ lng, const float* __restrict__ lnb, int N)
{
    extern __shared__ float sm[];
    float (*As)[66] = reinterpret_cast<float(*)[66]>(sm);          // [K][66] transposed A
    float (*Ws)[64] = reinterpret_cast<float(*)[64]>(sm + K * 66); // [K][64]

    const int tid  = threadIdx.x;
    const int row0 = blockIdx.y * 64;
    const int col0 = blockIdx.x * 64;
    const int tx   = tid & 7;      // cols tx*8 .. tx*8+7
    const int ty   = tid >> 3;     // rows ty*4 .. ty*4+3

    // Stage A (64 x K), transposed
    #pragma unroll
    for (int v = 0; v < K/8; v++) {
        int idx = tid + v * 128;
        int m   = idx / (K/4);
        int k4  = (idx % (K/4)) * 4;
        float4 t = *(const float4*)&A[(row0 + m) * K + k4];
        As[k4+0][m] = t.x; As[k4+1][m] = t.y; As[k4+2][m] = t.z; As[k4+3][m] = t.w;
    }
    // Stage W (K x 64)
    #pragma unroll
    for (int v = 0; v < K/8; v++) {
        int idx = tid + v * 128;
        int k   = idx >> 4;
        int n4  = (idx & 15) * 4;
        *(float4*)&Ws[k][n4] = *(const float4*)&W[k * N + col0 + n4];
    }
    __syncthreads();

    u64 acc[2][8];                 // [row-pair p][col j]
    #pragma unroll
    for (int p = 0; p < 2; p++)
        #pragma unroll
        for (int j = 0; j < 8; j++) acc[p][j] = 0ull;

    #pragma unroll 8
    for (int k = 0; k < K; k++) {
        u64 a01 = *(const u64*)&As[k][ty*4];
        u64 a23 = *(const u64*)&As[k][ty*4 + 2];
        float4 b0 = *(const float4*)&Ws[k][tx*8];
        float4 b1 = *(const float4*)&Ws[k][tx*8 + 4];
        u64 bd0 = pk2(b0.x,b0.x), bd1 = pk2(b0.y,b0.y), bd2 = pk2(b0.z,b0.z), bd3 = pk2(b0.w,b0.w);
        u64 bd4 = pk2(b1.x,b1.x), bd5 = pk2(b1.y,b1.y), bd6 = pk2(b1.z,b1.z), bd7 = pk2(b1.w,b1.w);
        ffma2(acc[0][0], a01, bd0); ffma2(acc[0][1], a01, bd1);
        ffma2(acc[0][2], a01, bd2); ffma2(acc[0][3], a01, bd3);
        ffma2(acc[0][4], a01, bd4); ffma2(acc[0][5], a01, bd5);
        ffma2(acc[0][6], a01, bd6); ffma2(acc[0][7], a01, bd7);
        ffma2(acc[1][0], a23, bd0); ffma2(acc[1][1], a23, bd1);
        ffma2(acc[1][2], a23, bd2); ffma2(acc[1][3], a23, bd3);
        ffma2(acc[1][4], a23, bd4); ffma2(acc[1][5], a23, bd5);
        ffma2(acc[1][6], a23, bd6); ffma2(acc[1][7], a23, bd7);
    }

    const int cb = col0 + tx * 8;
    float bj[8];
    #pragma unroll
    for (int j = 0; j < 8; j++) bj[j] = bias ? bias[cb + j] : 0.0f;

    float gj[8], eb[8];
    if (EPI == 2) {
        float4 g0 = *(const float4*)&lng[tx*8], g1 = *(const float4*)&lng[tx*8+4];
        float4 e0 = *(const float4*)&lnb[tx*8], e1 = *(const float4*)&lnb[tx*8+4];
        gj[0]=g0.x; gj[1]=g0.y; gj[2]=g0.z; gj[3]=g0.w; gj[4]=g1.x; gj[5]=g1.y; gj[6]=g1.z; gj[7]=g1.w;
        eb[0]=e0.x; eb[1]=e0.y; eb[2]=e0.z; eb[3]=e0.w; eb[4]=e1.x; eb[5]=e1.y; eb[6]=e1.z; eb[7]=e1.w;
    }

    #pragma unroll
    for (int p = 0; p < 2; p++) {
        int r0 = row0 + ty * 4 + p * 2;     // rows r0, r0+1
        float lo[8], hi[8];
        #pragma unroll
        for (int j = 0; j < 8; j++) {
            upk2(acc[p][j], lo[j], hi[j]);
            lo[j] += bj[j]; hi[j] += bj[j];
        }
        if (EPI == 1) {
            #pragma unroll
            for (int j = 0; j < 8; j++) { lo[j] = fmaxf(lo[j], 0.f); hi[j] = fmaxf(hi[j], 0.f); }
        }
        if (EPI == 2) {
            float4 r0a = *(const float4*)&res[r0*64 + cb];
            float4 r0b = *(const float4*)&res[r0*64 + cb + 4];
            float4 r1a = *(const float4*)&res[(r0+1)*64 + cb];
            float4 r1b = *(const float4*)&res[(r0+1)*64 + cb + 4];
            lo[0]+=r0a.x; lo[1]+=r0a.y; lo[2]+=r0a.z; lo[3]+=r0a.w;
            lo[4]+=r0b.x; lo[5]+=r0b.y; lo[6]+=r0b.z; lo[7]+=r0b.w;
            hi[0]+=r1a.x; hi[1]+=r1a.y; hi[2]+=r1a.z; hi[3]+=r1a.w;
            hi[4]+=r1b.x; hi[5]+=r1b.y; hi[6]+=r1b.z; hi[7]+=r1b.w;

            float s1l=0.f, s2l=0.f, s1h=0.f, s2h=0.f;
            #pragma unroll
            for (int j = 0; j < 8; j++) {
                s1l += lo[j]; s2l += lo[j]*lo[j];
                s1h += hi[j]; s2h += hi[j]*hi[j];
            }
            #pragma unroll
            for (int o = 1; o < 8; o <<= 1) {
                s1l += __shfl_xor_sync(0xFFFFFFFFu, s1l, o);
                s2l += __shfl_xor_sync(0xFFFFFFFFu, s2l, o);
                s1h += __shfl_xor_sync(0xFFFFFFFFu, s1h, o);
                s2h += __shfl_xor_sync(0xFFFFFFFFu, s2h, o);
            }
            float mul = s1l*(1.f/64.f), muh = s1h*(1.f/64.f);
            float rsl = rsqrtf(s2l*(1.f/64.f) - mul*mul + EPSF);
            float rsh = rsqrtf(s2h*(1.f/64.f) - muh*muh + EPSF);
            *(float4*)&Cout[r0*64+cb]       = make_float4(lo[0],lo[1],lo[2],lo[3]);
            *(float4*)&Cout[r0*64+cb+4]     = make_float4(lo[4],lo[5],lo[6],lo[7]);
            *(float4*)&Cout[(r0+1)*64+cb]   = make_float4(hi[0],hi[1],hi[2],hi[3]);
            *(float4*)&Cout[(r0+1)*64+cb+4] = make_float4(hi[4],hi[5],hi[6],hi[7]);
            float hl[8], hh[8];
            #pragma unroll
            for (int j = 0; j < 8; j++) {
                hl[j] = (lo[j]-mul)*rsl*gj[j] + eb[j];
                hh[j] = (hi[j]-muh)*rsh*gj[j] + eb[j];
            }
            *(float4*)&Hout[r0*64+cb]       = make_float4(hl[0],hl[1],hl[2],hl[3]);
            *(float4*)&Hout[r0*64+cb+4]     = make_float4(hl[4],hl[5],hl[6],hl[7]);
            *(float4*)&Hout[(r0+1)*64+cb]   = make_float4(hh[0],hh[1],hh[2],hh[3]);
            *(float4*)&Hout[(r0+1)*64+cb+4] = make_float4(hh[4],hh[5],hh[6],hh[7]);
        } else {
            *(float4*)&Cout[r0*N+cb]       = make_float4(lo[0],lo[1],lo[2],lo[3]);
            *(float4*)&Cout[r0*N+cb+4]     = make_float4(lo[4],lo[5],lo[6],lo[7]);
            *(float4*)&Cout[(r0+1)*N+cb]   = make_float4(hi[0],hi[1],hi[2],hi[3]);
            *(float4*)&Cout[(r0+1)*N+cb+4] = make_float4(hi[4],hi[5],hi[6],hi[7]);
        }
    }
}

// ---------------------------------------------------------------------------
// Fused QKV: one A-tile load feeds three weight panels (all resident in smem).
// ---------------------------------------------------------------------------
__global__ void __launch_bounds__(128)
qkv_k(const float* __restrict__ A,
      const float* __restrict__ wq, const float* __restrict__ wk, const float* __restrict__ wv,
      float* __restrict__ qo, float* __restrict__ ko, float* __restrict__ vo)
{
    extern __shared__ float sm[];
    float (*As)[66] = reinterpret_cast<float(*)[66]>(sm);            // [64][66]
    float (*Wq)[64] = reinterpret_cast<float(*)[64]>(sm + 64*66);
    float (*Wk)[64] = reinterpret_cast<float(*)[64]>(sm + 64*66 + 64*64);
    float (*Wv)[64] = reinterpret_cast<float(*)[64]>(sm + 64*66 + 2*64*64);

    const int tid  = threadIdx.x;
    const int row0 = blockIdx.y * 64;
    const int tx   = tid & 7;
    const int ty   = tid >> 3;

    #pragma unroll
    for (int v = 0; v < 8; v++) {
        int idx = tid + v * 128;
        int m   = idx >> 4;
        int k4  = (idx & 15) * 4;
        float4 t = *(const float4*)&A[(row0 + m) * 64 + k4];
        As[k4+0][m] = t.x; As[k4+1][m] = t.y; As[k4+2][m] = t.z; As[k4+3][m] = t.w;
    }
    #pragma unroll
    for (int v = 0; v < 8; v++) {
        int idx = tid + v * 128;
        int k   = idx >> 4;
        int n4  = (idx & 15) * 4;
        *(float4*)&Wq[k][n4] = *(const float4*)&wq[k * 64 + n4];
        *(float4*)&Wk[k][n4] = *(const float4*)&wk[k * 64 + n4];
        *(float4*)&Wv[k][n4] = *(const float4*)&wv[k * 64 + n4];
    }
    __syncthreads();

    u64 acc[3][2][8];
    #pragma unroll
    for (int m = 0; m < 3; m++)
        #pragma unroll
        for (int p = 0; p < 2; p++)
            #pragma unroll
            for (int j = 0; j < 8; j++) acc[m][p][j] = 0ull;

    #pragma unroll 4
    for (int k = 0; k < 64; k++) {
        u64 a01 = *(const u64*)&As[k][ty*4];
        u64 a23 = *(const u64*)&As[k][ty*4 + 2];
        #pragma unroll
        for (int m = 0; m < 3; m++) {
            const float* wrow = (m == 0) ? Wq[k] : (m == 1) ? Wk[k] : Wv[k];
            float4 b0 = *(const float4*)&wrow[tx*8];
            float4 b1 = *(const float4*)&wrow[tx*8 + 4];
            u64 bd0 = pk2(b0.x,b0.x), bd1 = pk2(b0.y,b0.y), bd2 = pk2(b0.z,b0.z), bd3 = pk2(b0.w,b0.w);
            u64 bd4 = pk2(b1.x,b1.x), bd5 = pk2(b1.y,b1.y), bd6 = pk2(b1.z,b1.z), bd7 = pk2(b1.w,b1.w);
            ffma2(acc[m][0][0], a01, bd0); ffma2(acc[m][0][1], a01, bd1);
            ffma2(acc[m][0][2], a01, bd2); ffma2(acc[m][0][3], a01, bd3);
            ffma2(acc[m][0][4], a01, bd4); ffma2(acc[m][0][5], a01, bd5);
            ffma2(acc[m][0][6], a01, bd6); ffma2(acc[m][0][7], a01, bd7);
            ffma2(acc[m][1][0], a23, bd0); ffma2(acc[m][1][1], a23, bd1);
            ffma2(acc[m][1][2], a23, bd2); ffma2(acc[m][1][3], a23, bd3);
            ffma2(acc[m][1][4], a23, bd4); ffma2(acc[m][1][5], a23, bd5);
            ffma2(acc[m][1][6], a23, bd6); ffma2(acc[m][1][7], a23, bd7);
        }
    }

    const int cb = tx * 8;
    #pragma unroll
    for (int m = 0; m < 3; m++) {
        float* O = (m == 0) ? qo : (m == 1) ? ko : vo;
        #pragma unroll
        for (int p = 0; p < 2; p++) {
            int r0 = row0 + ty * 4 + p * 2;
            float lo[8], hi[8];
            #pragma unroll
            for (int j = 0; j < 8; j++) upk2(acc[m][p][j], lo[j], hi[j]);
            *(float4*)&O[r0*64+cb]       = make_float4(lo[0],lo[1],lo[2],lo[3]);
            *(float4*)&O[r0*64+cb+4]     = make_float4(lo[4],lo[5],lo[6],lo[7]);
            *(float4*)&O[(r0+1)*64+cb]   = make_float4(hi[0],hi[1],hi[2],hi[3]);
            *(float4*)&O[(r0+1)*64+cb+4] = make_float4(hi[4],hi[5],hi[6],hi[7]);
        }
    }
}

// ---------------------------------------------------------------------------
// Embedding + first LayerNorm: warp per row.
// ---------------------------------------------------------------------------
__global__ void __launch_bounds__(256)
embed_ln_k(const int* __restrict__ idx, const float* __restrict__ tok,
           const float* __restrict__ pos, const float* __restrict__ g,
           const float* __restrict__ b, float* __restrict__ x, float* __restrict__ h)
{
    int row  = blockIdx.x * 8 + (threadIdx.x >> 5);
    int lane = threadIdx.x & 31;
    int t    = row & (Tc - 1);
    int tr   = idx[row];
    float v0 = tok[tr*Cn + lane]      + pos[t*Cn + lane];
    float v1 = tok[tr*Cn + lane + 32] + pos[t*Cn + lane + 32];
    float sum = v0 + v1;
    #pragma unroll
    for (int o = 16; o; o >>= 1) sum += __shfl_xor_sync(0xFFFFFFFFu, sum, o);
    float mu = sum * (1.f/64.f);
    float d0 = v0 - mu, d1 = v1 - mu;
    float vs = d0*d0 + d1*d1;
    #pragma unroll
    for (int o = 16; o; o >>= 1) vs += __shfl_xor_sync(0xFFFFFFFFu, vs, o);
    float r = rsqrtf(vs * (1.f/64.f) + EPSF);
    x[row*Cn + lane]      = v0;
    x[row*Cn + lane + 32] = v1;
    h[row*Cn + lane]      = d0*r*g[lane]    + b[lane];
    h[row*Cn + lane + 32] = d1*r*g[lane+32] + b[lane+32];
}

// ---------------------------------------------------------------------------
// Attention: block per (b,h). Bounded scores -> direct exp, no max chain.
// ---------------------------------------------------------------------------
__global__ void __launch_bounds__(256)
attn_kernel(const float* __restrict__ q, const float* __restrict__ kk,
            const float* __restrict__ vv, float* __restrict__ oo)
{
    int bh = blockIdx.x;
    int b  = bh >> 3;
    int h  = bh & 7;
    __shared__ float ks[Tc][12];
    __shared__ float vs[Tc][12];

    int tid  = threadIdx.x;
    int warp = tid >> 5;
    int lane = tid & 31;
    int base = b * Tc * Cn + h * HSn;

    {
        int r = tid;
        float4 a = *(const float4*)&kk[base + r*Cn];
        float4 c = *(const float4*)&kk[base + r*Cn + 4];
        *(float4*)&ks[r][0] = a; *(float4*)&ks[r][4] = c;
        a = *(const float4*)&vv[base + r*Cn];
        c = *(const float4*)&vv[base + r*Cn + 4];
        *(float4*)&vs[r][0] = a; *(float4*)&vs[r][4] = c;
    }
    __syncthreads();

    for (int rq = warp; rq < Tc/4; rq += 8) {
        int i0 = rq * 4;
        float qd[4][8];
        #pragma unroll
        for (int r2 = 0; r2 < 4; r2++) {
            float4 a = *(const float4*)&q[base + (i0+r2)*Cn];
            float4 c = *(const float4*)&q[base + (i0+r2)*Cn + 4];
            qd[r2][0]=a.x*0.125f; qd[r2][1]=a.y*0.125f; qd[r2][2]=a.z*0.125f; qd[r2][3]=a.w*0.125f;
            qd[r2][4]=c.x*0.125f; qd[r2][5]=c.y*0.125f; qd[r2][6]=c.z*0.125f; qd[r2][7]=c.w*0.125f;
        }
        float s[4] = {0.f, 0.f, 0.f, 0.f};
        float o[4][8];
        #pragma unroll
        for (int r2 = 0; r2 < 4; r2++)
            #pragma unroll
            for (int d = 0; d < 8; d++) o[r2][d] = 0.f;

        int imax = i0 + 3;
        for (int j = lane; j <= imax; j += 32) {
            float4 ka = *(const float4*)&ks[j][0];
            float4 kb = *(const float4*)&ks[j][4];
            float4 va = *(const float4*)&vs[j][0];
            float4 vb = *(const float4*)&vs[j][4];
            float kj[8] = {ka.x,ka.y,ka.z,ka.w,kb.x,kb.y,kb.z,kb.w};
            float vj[8] = {va.x,va.y,va.z,va.w,vb.x,vb.y,vb.z,vb.w};
            #pragma unroll
            for (int r2 = 0; r2 < 4; r2++) {
                float sc = 0.f;
                #pragma unroll
                for (int d = 0; d < 8; d++) sc = fmaf(qd[r2][d], kj[d], sc);
                if (j <= i0 + r2) {
                    float e = __expf(sc);
                    s[r2] += e;
                    #pragma unroll
                    for (int d = 0; d < 8; d++) o[r2][d] = fmaf(e, vj[d], o[r2][d]);
                }
            }
        }
        #pragma unroll
        for (int r2 = 0; r2 < 4; r2++) {
            #pragma unroll
            for (int off = 16; off; off >>= 1) {
                s[r2] += __shfl_xor_sync(0xFFFFFFFFu, s[r2], off);
                #pragma unroll
                for (int d = 0; d < 8; d++)
                    o[r2][d] += __shfl_xor_sync(0xFFFFFFFFu, o[r2][d], off);
            }
            if (lane == 0) {
                float inv = 1.f / s[r2];
                *(float4*)&oo[base + (i0+r2)*Cn]     = make_float4(o[r2][0]*inv, o[r2][1]*inv, o[r2][2]*inv, o[r2][3]*inv);
                *(float4*)&oo[base + (i0+r2)*Cn + 4] = make_float4(o[r2][4]*inv, o[r2][5]*inv, o[r2][6]*inv, o[r2][7]*inv);
            }
        }
    }
}

// ---------------------------------------------------------------------------
// Launch
// ---------------------------------------------------------------------------
#define SMEM_K64   ((64*66 + 64*64) * 4)          // 33280 B
#define SMEM_K256  ((256*66 + 256*64) * 4)        // 133120 B
#define SMEM_QKV   ((64*66 + 3*64*64) * 4)        // 66048 B

extern "C" void kernel_launch(void* const* d_in, const int* in_sizes, int n_in,
                              void* d_out, int out_size)
{
    const int*   idx    = (const int*)  d_in[0];
    const float* tok    = (const float*)d_in[1];
    const float* pos    = (const float*)d_in[2];
    const float* wq     = (const float*)d_in[3];
    const float* wk     = (const float*)d_in[4];
    const float* wv     = (const float*)d_in[5];
    const float* w_proj = (const float*)d_in[6];
    const float* b_proj = (const float*)d_in[7];
    const float* ln1_g  = (const float*)d_in[8];
    const float* ln1_b  = (const float*)d_in[9];
    const float* ln2_g  = (const float*)d_in[10];
    const float* ln2_b  = (const float*)d_in[11];
    const float* w1     = (const float*)d_in[12];
    const float* b1     = (const float*)d_in[13];
    const float* w2     = (const float*)d_in[14];
    const float* b2     = (const float*)d_in[15];
    const float* lnf_g  = (const float*)d_in[16];
    const float* lnf_b  = (const float*)d_in[17];
    const float* w_head = (const float*)d_in[18];
    const float* b_head = (const float*)d_in[19];
    float* out = (float*)d_out;

    // Opt-in to >48KB dynamic smem (host-side, capture-safe, idempotent)
    cudaFuncSetAttribute(gemm_k<256,2>, cudaFuncAttributeMaxDynamicSharedMemorySize, SMEM_K256);
    cudaFuncSetAttribute(qkv_k,         cudaFuncAttributeMaxDynamicSharedMemorySize, SMEM_QKV);
    cudaFuncSetAttribute(gemm_k<64,0>,  cudaFuncAttributeMaxDynamicSharedMemorySize, SMEM_K64);
    cudaFuncSetAttribute(gemm_k<64,1>,  cudaFuncAttributeMaxDynamicSharedMemorySize, SMEM_K64);
    cudaFuncSetAttribute(gemm_k<64,2>,  cudaFuncAttributeMaxDynamicSharedMemorySize, SMEM_K64);

    void* sp = nullptr;
    cudaGetSymbolAddress(&sp, g_scratch);
    float* g_x  = (float*)sp;
    float* g_h  = g_x + SZ_XC;
    float* g_q  = g_h + SZ_XC;
    float* g_k  = g_q + SZ_XC;
    float* g_v  = g_k + SZ_XC;
    float* g_o  = g_v + SZ_XC;
    float* g_ff = g_o + SZ_XC;

    embed_ln_k<<<BT/8, 256>>>(idx, tok, pos, ln1_g, ln1_b, g_x, g_h);

    for (int l = 0; l < Ln; l++) {
        qkv_k<<<dim3(1, 256), 128, SMEM_QKV>>>(g_h, wq + l*Cn*Cn, wk + l*Cn*Cn, wv + l*Cn*Cn,
                                               g_q, g_k, g_v);
        attn_kernel<<<Bc*Hn, 256>>>(g_q, g_k, g_v, g_o);
        gemm_k<64,2><<<dim3(1, 256), 128, SMEM_K64>>>(g_o, w_proj + l*Cn*Cn, b_proj + l*Cn, g_x,
                                                      g_x, g_h, ln2_g + l*Cn, ln2_b + l*Cn, 64);
        gemm_k<64,1><<<dim3(4, 256), 128, SMEM_K64>>>(g_h, w1 + l*Cn*DFF, b1 + l*DFF, nullptr,
                                                      g_ff, nullptr, nullptr, nullptr, DFF);
        const float* ng = (l < Ln-1) ? ln1_g + (l+1)*Cn : lnf_g;
        const float* nb = (l < Ln-1) ? ln1_b + (l+1)*Cn : lnf_b;
        gemm_k<256,2><<<dim3(1, 256), 128, SMEM_K256>>>(g_ff, w2 + l*DFF*Cn, b2 + l*Cn, g_x,
                                                        g_x, g_h, ng, nb, 64);
    }

    gemm_k<64,0><<<dim3(VOC/64, 256), 128, SMEM_K64>>>(g_h, w_head, b_head, nullptr,
                                                       out, nullptr, nullptr, nullptr, VOC);
}